// round 2
// baseline (speedup 1.0000x reference)
#include <cuda_runtime.h>
#include <cuda_bf16.h>

// Problem shape (fixed by setup_inputs)
#define B_ 8
#define T_ 2048
#define D_ 2048
#define M_ (B_ * T_)   // 16384 rows

// Scratch for P = x @ Wp^T + bp  (134 MB) — device global (no allocations allowed)
__device__ float g_P[(size_t)M_ * (size_t)D_];

// ---------------------------------------------------------------------------
// GEMM: P[m][n] = sum_k X[m][k] * W[n][k] + bias[n]
// X: [M, K] row-major, W: [N, K] row-major (both K-contiguous -> TN GEMM)
// Tiling: 128x128x16, 256 threads, 8x8 accumulator per thread.
// ---------------------------------------------------------------------------
#define BM 128
#define BN 128
#define BK 16

__global__ __launch_bounds__(256, 2)
void braid_gemm_kernel(const float* __restrict__ X,
                       const float* __restrict__ W,
                       const float* __restrict__ bias,
                       float* __restrict__ P) {
    __shared__ float As[BK][BM];
    __shared__ float Bs[BK][BN];

    const int tid = threadIdx.x;
    const int bm = blockIdx.y * BM;
    const int bn = blockIdx.x * BN;
    const int tx = tid & 15;   // n-direction (8 cols each)
    const int ty = tid >> 4;   // m-direction (8 rows each)

    float acc[8][8];
#pragma unroll
    for (int i = 0; i < 8; i++)
#pragma unroll
        for (int j = 0; j < 8; j++) acc[i][j] = 0.0f;

    // Cooperative load mapping: 512 float4 per tile, 2 per thread.
    const int lrow = tid >> 2;  // 0..63
    const int lkg  = tid & 3;   // k-group of 4 floats

    for (int k0 = 0; k0 < D_; k0 += BK) {
#pragma unroll
        for (int h = 0; h < 2; h++) {
            const int row = lrow + h * 64;
            float4 v = *reinterpret_cast<const float4*>(
                &X[(size_t)(bm + row) * D_ + k0 + lkg * 4]);
            As[lkg * 4 + 0][row] = v.x;
            As[lkg * 4 + 1][row] = v.y;
            As[lkg * 4 + 2][row] = v.z;
            As[lkg * 4 + 3][row] = v.w;
        }
#pragma unroll
        for (int h = 0; h < 2; h++) {
            const int row = lrow + h * 64;
            float4 v = *reinterpret_cast<const float4*>(
                &W[(size_t)(bn + row) * D_ + k0 + lkg * 4]);
            Bs[lkg * 4 + 0][row] = v.x;
            Bs[lkg * 4 + 1][row] = v.y;
            Bs[lkg * 4 + 2][row] = v.z;
            Bs[lkg * 4 + 3][row] = v.w;
        }
        __syncthreads();

#pragma unroll
        for (int k = 0; k < BK; k++) {
            float a[8], b[8];
#pragma unroll
            for (int i = 0; i < 8; i++) a[i] = As[k][ty * 8 + i];
#pragma unroll
            for (int j = 0; j < 8; j++) b[j] = Bs[k][tx * 8 + j];
#pragma unroll
            for (int i = 0; i < 8; i++)
#pragma unroll
                for (int j = 0; j < 8; j++)
                    acc[i][j] = fmaf(a[i], b[j], acc[i][j]);
        }
        __syncthreads();
    }

    // Epilogue: add bias, write P (vectorized)
#pragma unroll
    for (int i = 0; i < 8; i++) {
        const int m = bm + ty * 8 + i;
#pragma unroll
        for (int j = 0; j < 8; j += 4) {
            const int n = bn + tx * 8 + j;
            float4 o;
            o.x = acc[i][j + 0] + bias[n + 0];
            o.y = acc[i][j + 1] + bias[n + 1];
            o.z = acc[i][j + 2] + bias[n + 2];
            o.w = acc[i][j + 3] + bias[n + 3];
            *reinterpret_cast<float4*>(&P[(size_t)m * D_ + n]) = o;
        }
    }
}

// ---------------------------------------------------------------------------
// LN epilogue. One block (256 threads) per row r = b*T + t.
//   t == 0    : out = LN(x + P[r+1]/6)
//   t == T-1  : out = LN(x + P[r-1]/6)
//   else      : out = LN( LN(x + P[r-1]/6) + P[r+1]/6 )
// Two-pass mean/var per LN (matches jnp.mean / mean((v-mu)^2)).
// ---------------------------------------------------------------------------
__device__ __forceinline__ float block_reduce_sum(float v, float* sbuf) {
#pragma unroll
    for (int o = 16; o > 0; o >>= 1) v += __shfl_xor_sync(0xffffffffu, v, o);
    const int w = threadIdx.x >> 5;
    if ((threadIdx.x & 31) == 0) sbuf[w] = v;
    __syncthreads();
    if (threadIdx.x < 32) {
        float r = (threadIdx.x < 8) ? sbuf[threadIdx.x] : 0.0f;
#pragma unroll
        for (int o = 4; o > 0; o >>= 1) r += __shfl_xor_sync(0xffffffffu, r, o);
        if (threadIdx.x == 0) sbuf[8] = r;
    }
    __syncthreads();
    return sbuf[8];
}

#define VPT 8  // 2048 / 256

__global__ __launch_bounds__(256)
void braid_epilogue_kernel(const float* __restrict__ X,
                           const float* __restrict__ P,
                           const float* __restrict__ gamma,
                           const float* __restrict__ beta,
                           float* __restrict__ out) {
    __shared__ float sbuf[9];
    const int r = blockIdx.x;
    const int t = r & (T_ - 1);
    const int tid = threadIdx.x;
    const float inv6 = 1.0f / 6.0f;
    const float invD = 1.0f / (float)D_;

    const size_t base = (size_t)r * D_;
    const float* Pprev = P + base - D_;  // only dereferenced when t > 0
    const float* Pnext = P + base + D_;  // only dereferenced when t < T-1

    float v[VPT];
    if (t == 0) {
#pragma unroll
        for (int i = 0; i < VPT; i++) {
            const int d = tid + i * 256;
            v[i] = X[base + d] + inv6 * Pnext[d];
        }
    } else {
#pragma unroll
        for (int i = 0; i < VPT; i++) {
            const int d = tid + i * 256;
            v[i] = X[base + d] + inv6 * Pprev[d];
        }
    }

    // ---- LN #1 ----
    {
        float s = 0.0f;
#pragma unroll
        for (int i = 0; i < VPT; i++) s += v[i];
        const float mu = block_reduce_sum(s, sbuf) * invD;
        float q = 0.0f;
#pragma unroll
        for (int i = 0; i < VPT; i++) { const float c = v[i] - mu; q += c * c; }
        const float var = block_reduce_sum(q, sbuf) * invD;
        const float rs = rsqrtf(var + 1e-5f);
#pragma unroll
        for (int i = 0; i < VPT; i++) {
            const int d = tid + i * 256;
            v[i] = (v[i] - mu) * rs * gamma[d] + beta[d];
        }
    }

    // ---- middle rows: add next-P contribution and LN again ----
    if (t != 0 && t != T_ - 1) {
#pragma unroll
        for (int i = 0; i < VPT; i++) {
            const int d = tid + i * 256;
            v[i] += inv6 * Pnext[d];
        }
        float s = 0.0f;
#pragma unroll
        for (int i = 0; i < VPT; i++) s += v[i];
        const float mu = block_reduce_sum(s, sbuf) * invD;
        float q = 0.0f;
#pragma unroll
        for (int i = 0; i < VPT; i++) { const float c = v[i] - mu; q += c * c; }
        const float var = block_reduce_sum(q, sbuf) * invD;
        const float rs = rsqrtf(var + 1e-5f);
#pragma unroll
        for (int i = 0; i < VPT; i++) {
            const int d = tid + i * 256;
            v[i] = (v[i] - mu) * rs * gamma[d] + beta[d];
        }
    }

#pragma unroll
    for (int i = 0; i < VPT; i++) {
        const int d = tid + i * 256;
        out[base + d] = v[i];
    }
}

// ---------------------------------------------------------------------------
// Launch. Input order (metadata): x, W1, b1, W2, b2, Wp, bp, gamma, beta.
// W1/b1/W2/b2 are provably dead (mean of softmax over its own axis == 1/6).
// ---------------------------------------------------------------------------
extern "C" void kernel_launch(void* const* d_in, const int* in_sizes, int n_in,
                              void* d_out, int out_size) {
    const float* x     = (const float*)d_in[0];
    const float* Wp    = (const float*)d_in[5];
    const float* bp    = (const float*)d_in[6];
    const float* gamma = (const float*)d_in[7];
    const float* beta  = (const float*)d_in[8];
    float* out = (float*)d_out;

    float* P;
    cudaGetSymbolAddress((void**)&P, g_P);

    dim3 ggrid(D_ / BN, M_ / BM);   // (16, 128)
    braid_gemm_kernel<<<ggrid, 256>>>(x, Wp, bp, P);
    braid_epilogue_kernel<<<M_, 256>>>(x, P, gamma, beta, out);
}

// round 5
// speedup vs baseline: 6.5459x; 6.5459x over previous
#include <cuda_runtime.h>
#include <cuda_bf16.h>

// ---------------------------------------------------------------------------
// Problem shape (fixed by setup_inputs)
// ---------------------------------------------------------------------------
#define B_ 8
#define T_ 2048
#define D_ 2048
#define M_ (B_ * T_)   // 16384 rows

// Scratch for P = x @ Wp^T + bp
__device__ float g_P[(size_t)M_ * (size_t)D_];

// ---------------------------------------------------------------------------
// tf32 helpers (mma.sync path — works on plain sm_103 target, no 'a' needed)
// ---------------------------------------------------------------------------
__device__ __forceinline__ unsigned f2tf32(float f) {
    unsigned r;
    asm("cvt.rna.tf32.f32 %0, %1;" : "=r"(r) : "f"(f));
    return r;
}

__device__ __forceinline__ void mma_tf32(float* c, const unsigned* a, const unsigned* b) {
    asm volatile(
        "mma.sync.aligned.m16n8k8.row.col.f32.tf32.tf32.f32 "
        "{%0,%1,%2,%3}, {%4,%5,%6,%7}, {%8,%9}, {%0,%1,%2,%3};"
        : "+f"(c[0]), "+f"(c[1]), "+f"(c[2]), "+f"(c[3])
        : "r"(a[0]), "r"(a[1]), "r"(a[2]), "r"(a[3]), "r"(b[0]), "r"(b[1]));
}

// ---------------------------------------------------------------------------
// GEMM: P[m][n] = sum_k X[m][k] * W[n][k] + bias[n]     (TN, both K-contiguous)
// CTA tile 128x256, K-chunk 32, 256 threads, warp grid 2x4 of 64x64 tiles.
//
// SMEM fragment-major layout (per k-step of 8):
//   A: lane l holds a[0..3] -> one LDS.128 at  A + ks*1028 + mt*128 + l*4
//   B: lane l holds b[0..1] -> one LDS.64  at  B + ks*2050 + nt*64  + l*2
// k-step strides 1028/2050 (not mult. of 32) spread producer STS banks.
// ---------------------------------------------------------------------------
#define BM 128
#define BN 256
#define KB 32
#define NCHUNK (D_ / KB)          // 64
#define A_KS 1028                 // floats per k-step block (8 mtiles*128 + 4 pad)
#define B_KS 2050                 // floats per k-step block (32 ntiles*64 + 2 pad)
#define A_FLOATS (3 * A_KS + 8 * 128)    // 4108
#define B_OFF A_FLOATS                   // B starts right after A
#define STAGE_FLOATS (A_FLOATS + 3 * B_KS + 32 * 64)   // 12306 -> pad to 12308
#define STAGE_PAD 12308
#define SMEM_BYTES (2 * STAGE_PAD * 4)   // 98464

__global__ __launch_bounds__(256, 1)
void braid_gemm_mma(const float* __restrict__ X,
                    const float* __restrict__ W,
                    const float* __restrict__ bias,
                    float* __restrict__ P) {
    extern __shared__ __align__(16) unsigned smem[];
    const int tid  = threadIdx.x;
    const int lane = tid & 31;
    const int wrp  = tid >> 5;          // 0..7
    const int wm   = wrp >> 2;          // 0..1  (m dir, 64 rows)
    const int wn   = wrp & 3;           // 0..3  (n dir, 64 cols)
    const int bm   = blockIdx.y * BM;
    const int bn   = blockIdx.x * BN;

    const float* Xb = X + (size_t)bm * D_;
    const float* Wb = W + (size_t)bn * D_;

    float acc[4][8][4];
#pragma unroll
    for (int q = 0; q < 4; q++)
#pragma unroll
        for (int p = 0; p < 8; p++)
#pragma unroll
            for (int e = 0; e < 4; e++) acc[q][p][e] = 0.0f;

    float4 ar[4], br[8];

    // ---- gmem -> regs (coalesced float4) ----
    auto ldg_chunk = [&](int c) {
        const int k0 = c * KB;
#pragma unroll
        for (int i = 0; i < 4; i++) {
            const int f = tid + i * 256;                    // A: 1024 float4
            ar[i] = *reinterpret_cast<const float4*>(
                Xb + (size_t)(f >> 3) * D_ + k0 + (f & 7) * 4);
        }
#pragma unroll
        for (int i = 0; i < 8; i++) {
            const int f = tid + i * 256;                    // B: 2048 float4
            br[i] = *reinterpret_cast<const float4*>(
                Wb + (size_t)(f >> 3) * D_ + k0 + (f & 7) * 4);
        }
    };

    // ---- regs -> smem fragment-major (with tf32 convert) ----
    auto sts_chunk = [&](int s) {
        unsigned* As = smem + s * STAGE_PAD;
        unsigned* Bs = As + B_OFF;
#pragma unroll
        for (int i = 0; i < 4; i++) {
            const int f = tid + i * 256;
            const int row = f >> 3, c4 = f & 7;
            const int ks = c4 >> 1;
            const int reg = ((row >> 3) & 1) | ((c4 & 1) << 1);
            const int base = ks * A_KS + (row >> 4) * 128 + ((row & 7) * 4) * 4 + reg;
            As[base +  0] = f2tf32(ar[i].x);
            As[base +  4] = f2tf32(ar[i].y);
            As[base +  8] = f2tf32(ar[i].z);
            As[base + 12] = f2tf32(ar[i].w);
        }
#pragma unroll
        for (int i = 0; i < 8; i++) {
            const int f = tid + i * 256;
            const int row = f >> 3, c4 = f & 7;
            const int ks = c4 >> 1;
            const int reg = c4 & 1;
            const int base = ks * B_KS + (row >> 3) * 64 + ((row & 7) * 4) * 2 + reg;
            Bs[base + 0] = f2tf32(br[i].x);
            Bs[base + 2] = f2tf32(br[i].y);
            Bs[base + 4] = f2tf32(br[i].z);
            Bs[base + 6] = f2tf32(br[i].w);
        }
    };

    ldg_chunk(0);
    sts_chunk(0);
    __syncthreads();

    for (int c = 0; c < NCHUNK; c++) {
        if (c + 1 < NCHUNK) ldg_chunk(c + 1);

        const unsigned* As = smem + (c & 1) * STAGE_PAD;
        const unsigned* Bs = As + B_OFF;
#pragma unroll
        for (int ks = 0; ks < 4; ks++) {
            unsigned a[4][4], b[8][2];
#pragma unroll
            for (int q = 0; q < 4; q++) {
                uint4 v = *reinterpret_cast<const uint4*>(
                    As + ks * A_KS + (wm * 4 + q) * 128 + lane * 4);
                a[q][0] = v.x; a[q][1] = v.y; a[q][2] = v.z; a[q][3] = v.w;
            }
#pragma unroll
            for (int p = 0; p < 8; p++) {
                uint2 v = *reinterpret_cast<const uint2*>(
                    Bs + ks * B_KS + (wn * 8 + p) * 64 + lane * 2);
                b[p][0] = v.x; b[p][1] = v.y;
            }
#pragma unroll
            for (int q = 0; q < 4; q++)
#pragma unroll
                for (int p = 0; p < 8; p++)
                    mma_tf32(acc[q][p], a[q], b[p]);
        }

        if (c + 1 < NCHUNK) {
            sts_chunk((c + 1) & 1);
            __syncthreads();
        }
    }

    // ---- epilogue: bias + store (float2 per frag half) ----
#pragma unroll
    for (int q = 0; q < 4; q++) {
        const int gr = bm + wm * 64 + q * 16 + (lane >> 2);
#pragma unroll
        for (int p = 0; p < 8; p++) {
            const int gc = bn + wn * 64 + p * 8 + (lane & 3) * 2;
            const float2 bv = *reinterpret_cast<const float2*>(bias + gc);
            float2 o0 = make_float2(acc[q][p][0] + bv.x, acc[q][p][1] + bv.y);
            float2 o1 = make_float2(acc[q][p][2] + bv.x, acc[q][p][3] + bv.y);
            *reinterpret_cast<float2*>(&P[(size_t)gr * D_ + gc])       = o0;
            *reinterpret_cast<float2*>(&P[(size_t)(gr + 8) * D_ + gc]) = o1;
        }
    }
}

// ---------------------------------------------------------------------------
// LN epilogue (float4-ized). One block (256 threads) per row r = b*T + t.
//   t == 0    : out = LN(x + P[r+1]/6)
//   t == T-1  : out = LN(x + P[r-1]/6)
//   else      : out = LN( LN(x + P[r-1]/6) + P[r+1]/6 )
// ---------------------------------------------------------------------------
__device__ __forceinline__ float block_reduce_sum(float v, float* sbuf) {
#pragma unroll
    for (int o = 16; o > 0; o >>= 1) v += __shfl_xor_sync(0xffffffffu, v, o);
    const int w = threadIdx.x >> 5;
    if ((threadIdx.x & 31) == 0) sbuf[w] = v;
    __syncthreads();
    if (threadIdx.x < 32) {
        float r = (threadIdx.x < 8) ? sbuf[threadIdx.x] : 0.0f;
#pragma unroll
        for (int o = 4; o > 0; o >>= 1) r += __shfl_xor_sync(0xffffffffu, r, o);
        if (threadIdx.x == 0) sbuf[8] = r;
    }
    __syncthreads();
    return sbuf[8];
}

__global__ __launch_bounds__(256)
void braid_epilogue_kernel(const float* __restrict__ X,
                           const float* __restrict__ P,
                           const float* __restrict__ gamma,
                           const float* __restrict__ beta,
                           float* __restrict__ out) {
    __shared__ float sbuf[9];
    const int r = blockIdx.x;
    const int t = r & (T_ - 1);
    const int tid = threadIdx.x;
    const float inv6 = 1.0f / 6.0f;
    const float invD = 1.0f / (float)D_;

    const size_t base = (size_t)r * D_;
    const int d0 = tid * 4, d1 = 1024 + tid * 4;

    float v[8], g[8], be[8];
    {
        const float4 ga = *reinterpret_cast<const float4*>(gamma + d0);
        const float4 gb = *reinterpret_cast<const float4*>(gamma + d1);
        const float4 ba = *reinterpret_cast<const float4*>(beta + d0);
        const float4 bb = *reinterpret_cast<const float4*>(beta + d1);
        g[0]=ga.x; g[1]=ga.y; g[2]=ga.z; g[3]=ga.w; g[4]=gb.x; g[5]=gb.y; g[6]=gb.z; g[7]=gb.w;
        be[0]=ba.x; be[1]=ba.y; be[2]=ba.z; be[3]=ba.w; be[4]=bb.x; be[5]=bb.y; be[6]=bb.z; be[7]=bb.w;
    }
    {
        const size_t nb = (t == 0) ? base + D_ : base - D_;   // Pnext for t==0, else Pprev
        const float4 xa = *reinterpret_cast<const float4*>(X + base + d0);
        const float4 xb = *reinterpret_cast<const float4*>(X + base + d1);
        const float4 pa = *reinterpret_cast<const float4*>(P + nb + d0);
        const float4 pb = *reinterpret_cast<const float4*>(P + nb + d1);
        v[0]=xa.x+inv6*pa.x; v[1]=xa.y+inv6*pa.y; v[2]=xa.z+inv6*pa.z; v[3]=xa.w+inv6*pa.w;
        v[4]=xb.x+inv6*pb.x; v[5]=xb.y+inv6*pb.y; v[6]=xb.z+inv6*pb.z; v[7]=xb.w+inv6*pb.w;
    }
    // ---- LN #1 ----
    {
        float s = 0.0f;
#pragma unroll
        for (int i = 0; i < 8; i++) s += v[i];
        const float mu = block_reduce_sum(s, sbuf) * invD;
        float q = 0.0f;
#pragma unroll
        for (int i = 0; i < 8; i++) { const float c = v[i] - mu; q += c * c; }
        const float rs = rsqrtf(block_reduce_sum(q, sbuf) * invD + 1e-5f);
#pragma unroll
        for (int i = 0; i < 8; i++) v[i] = (v[i] - mu) * rs * g[i] + be[i];
    }
    // ---- middle rows: add Pnext/6 and LN again ----
    if (t != 0 && t != T_ - 1) {
        const size_t nb = base + D_;
        const float4 pa = *reinterpret_cast<const float4*>(P + nb + d0);
        const float4 pb = *reinterpret_cast<const float4*>(P + nb + d1);
        v[0]+=inv6*pa.x; v[1]+=inv6*pa.y; v[2]+=inv6*pa.z; v[3]+=inv6*pa.w;
        v[4]+=inv6*pb.x; v[5]+=inv6*pb.y; v[6]+=inv6*pb.z; v[7]+=inv6*pb.w;
        float s = 0.0f;
#pragma unroll
        for (int i = 0; i < 8; i++) s += v[i];
        const float mu = block_reduce_sum(s, sbuf) * invD;
        float q = 0.0f;
#pragma unroll
        for (int i = 0; i < 8; i++) { const float c = v[i] - mu; q += c * c; }
        const float rs = rsqrtf(block_reduce_sum(q, sbuf) * invD + 1e-5f);
#pragma unroll
        for (int i = 0; i < 8; i++) v[i] = (v[i] - mu) * rs * g[i] + be[i];
    }
    *reinterpret_cast<float4*>(out + base + d0) = make_float4(v[0], v[1], v[2], v[3]);
    *reinterpret_cast<float4*>(out + base + d1) = make_float4(v[4], v[5], v[6], v[7]);
}

// ---------------------------------------------------------------------------
// Launch. Inputs: x, W1, b1, W2, b2, Wp, bp, gamma, beta.
// W1/b1/W2/b2 dead: mean(softmax(logits)) over the softmax axis == 1/6 exactly.
// ---------------------------------------------------------------------------
extern "C" void kernel_launch(void* const* d_in, const int* in_sizes, int n_in,
                              void* d_out, int out_size) {
    const float* x     = (const float*)d_in[0];
    const float* Wp    = (const float*)d_in[5];
    const float* bp    = (const float*)d_in[6];
    const float* gamma = (const float*)d_in[7];
    const float* beta  = (const float*)d_in[8];
    float* out = (float*)d_out;

    float* P;
    cudaGetSymbolAddress((void**)&P, g_P);

    cudaFuncSetAttribute(braid_gemm_mma, cudaFuncAttributeMaxDynamicSharedMemorySize, SMEM_BYTES);

    dim3 ggrid(D_ / BN, M_ / BM);   // (8, 128): x-fastest -> A-tile L2 reuse, W L2-resident
    braid_gemm_mma<<<ggrid, 256, SMEM_BYTES>>>(x, Wp, bp, P);
    braid_epilogue_kernel<<<M_, 256>>>(x, P, gamma, beta, out);
}